// round 5
// baseline (speedup 1.0000x reference)
#include <cuda_runtime.h>
#include <math.h>

#define B_ 64
#define C_ 3
#define N_ 512

__global__ void __launch_bounds__(256, 3)
diffeo_kernel(const float* __restrict__ x,
              const float* __restrict__ Fx,
              const float* __restrict__ Fy,
              float* __restrict__ out,
              float scale) {
    __shared__ float gsh[2][8];   // [row][0..3]=gu_i, [row][4..7]=gv_i

    const int tid = threadIdx.x;
    const int b   = blockIdx.y;
    const int y0  = blockIdx.x * 2;

    const float PI_INV = (float)M_PI / (float)(N_ - 1);

    // 16 threads: fold y-dependence + envelope into per-row coeffs.
    if (tid < 16) {
        const int  i    = tid & 3;
        const int  isV  = (tid >> 2) & 1;
        const int  row  = (tid >> 3) & 1;
        const float* F  = (isV ? Fy : Fx) + b * 16 + i * 4;
        const float py  = (float)(y0 + row) * PI_INV;
        const float ki  = (float)(i + 1);
        float acc = 0.0f;
#pragma unroll
        for (int j = 0; j < 4; j++) {
            float kj = (float)(j + 1);
            float r  = sqrtf(ki * ki + kj * kj);
            float e  = (r < 4.5f) ? (1.0f / r) : 0.0f;
            float sj = __sinf(py * (float)(j + 1));
            acc = fmaf(F[j] * e, sj, acc);
        }
        gsh[row][(isV << 2) | i] = acc;
    }
    __syncthreads();

    const int warp = tid >> 5;
    const int lane = tid & 31;
    const int row  = warp >> 2;          // which row of the pair
    const int seg  = warp & 3;           // 128-px segment within row
    const int y    = y0 + row;
    const int xb   = seg * 128 + lane;   // base pixel; +32 per k

    const float gu0 = gsh[row][0], gu1 = gsh[row][1], gu2 = gsh[row][2], gu3 = gsh[row][3];
    const float gv0 = gsh[row][4], gv1 = gsh[row][5], gv2 = gsh[row][6], gv3 = gsh[row][7];

    const int img_stride = N_ * N_;
    const char*  imgB = (const char*)(x + (size_t)b * C_ * img_stride);
    float*       orow = out + (size_t)b * C_ * img_stride + y * N_;

    // Incremental sin over k: angle step = 32 * PI_INV
    float s1 = __sinf((float)xb * PI_INV);
    float c1 = __cosf((float)xb * PI_INV);
    const float stepA = 32.0f * PI_INV;
    const float sd = __sinf(stepA);
    const float cd = __cosf(stepA);

    const float fy = (float)y;

    // ---- Phase 1: addresses + weights for all 4 pixels (no memory deps) ----
    unsigned off00[4];
    int dxB[4], dyB[4];
    float w00[4], w01[4], w10[4], w11[4];

#pragma unroll
    for (int k = 0; k < 4; k++) {
        const int xi = xb + k * 32;

        const float s2 = 2.0f * s1 * c1;
        const float c2 = fmaf(2.0f * c1, c1, -1.0f);
        const float s3 = fmaf(s1, c2, c1 * s2);
        const float s4 = 2.0f * s2 * c2;

        const float u = fmaf(gu0, s1, fmaf(gu1, s2, fmaf(gu2, s3, gu3 * s4)));
        const float v = fmaf(gv0, s1, fmaf(gv1, s2, fmaf(gv2, s3, gv3 * s4)));

        float xn = fminf(fmaxf((float)xi - scale * u, 0.0f), (float)(N_ - 1));
        float yn = fminf(fmaxf(fy        - scale * v, 0.0f), (float)(N_ - 1));

        const float xff = floorf(xn);
        const float yff = floorf(yn);
        const int   xf  = (int)xff;
        const int   yf  = (int)yff;
        const float xv  = xn - xff;
        const float yv  = yn - yff;

        // ceil == floor+1 clamped; weight is exactly 0 at integer coords,
        // so the substituted in-bounds tap never contributes.
        dxB[k] = (xf < N_ - 1) ? 4      : 0;
        dyB[k] = (yf < N_ - 1) ? 4 * N_ : 0;

        w00[k] = (1.0f - yv) * (1.0f - xv);
        w01[k] = (1.0f - yv) * xv;
        w10[k] = yv * (1.0f - xv);
        w11[k] = yv * xv;

        off00[k] = (unsigned)(yf * N_ + xf) << 2;

        const float ns = fmaf(s1, cd,  c1 * sd);
        const float nc = fmaf(c1, cd, -s1 * sd);
        s1 = ns; c1 = nc;
    }

    // ---- Phase 2: gathers in 24-load batches (2 pixels x 3 channels x 4 taps) ----
#pragma unroll
    for (int kk = 0; kk < 2; kk++) {
        float t[2][3][4];

#pragma unroll
        for (int p = 0; p < 2; p++) {
            const int k = kk * 2 + p;
            const char* a00 = imgB + off00[k];
            const char* a01 = a00 + dxB[k];
            const char* a10 = a00 + dyB[k];
            const char* a11 = a10 + dxB[k];
#pragma unroll
            for (int c = 0; c < C_; c++) {
                const int cb = c * img_stride * 4;
                t[p][c][0] = __ldg((const float*)(a00 + cb));
                t[p][c][1] = __ldg((const float*)(a01 + cb));
                t[p][c][2] = __ldg((const float*)(a10 + cb));
                t[p][c][3] = __ldg((const float*)(a11 + cb));
            }
        }

#pragma unroll
        for (int p = 0; p < 2; p++) {
            const int k = kk * 2 + p;
            const int xi = xb + k * 32;
#pragma unroll
            for (int c = 0; c < C_; c++) {
                float val = fmaf(w00[k], t[p][c][0],
                            fmaf(w01[k], t[p][c][1],
                            fmaf(w10[k], t[p][c][2],
                                 w11[k] * t[p][c][3])));
                orow[c * img_stride + xi] = val;   // dense 128B store per warp
            }
        }
    }
}

extern "C" void kernel_launch(void* const* d_in, const int* in_sizes, int n_in,
                              void* d_out, int out_size) {
    const float* x  = (const float*)d_in[0];
    const float* Fx = (const float*)d_in[1];
    const float* Fy = (const float*)d_in[2];
    float* out = (float*)d_out;

    const double n_d  = (double)N_;
    const double typ  = n_d * sqrt(M_PI * log(4.0)) / 2.0;
    const double T    = 0.01;
    const float scale = (float)(sqrt(T / (typ * typ)) * n_d);

    dim3 block(256);
    dim3 grid(N_ / 2, B_);   // two rows per block
    diffeo_kernel<<<grid, block>>>(x, Fx, Fy, out, scale);
}

// round 6
// speedup vs baseline: 1.2124x; 1.2124x over previous
#include <cuda_runtime.h>
#include <math.h>

#define B_ 64
#define C_ 3
#define N_ 512

__global__ void __launch_bounds__(256)
diffeo_kernel(const float* __restrict__ x,
              const float* __restrict__ Fx,
              const float* __restrict__ Fy,
              float* __restrict__ out,
              float scale) {
    __shared__ float gsh[2][8];   // [row][0..3]=gu_i, [row][4..7]=gv_i

    const int tid = threadIdx.x;
    const int b   = blockIdx.y;
    const int y0  = blockIdx.x * 2;

    const float PI_INV = (float)M_PI / (float)(N_ - 1);

    // 16 threads: fold y-dependence + envelope into per-row coeffs.
    if (tid < 16) {
        const int  i    = tid & 3;
        const int  isV  = (tid >> 2) & 1;
        const int  row  = (tid >> 3) & 1;
        const float* F  = (isV ? Fy : Fx) + b * 16 + i * 4;
        const float py  = (float)(y0 + row) * PI_INV;
        const float ki  = (float)(i + 1);
        float acc = 0.0f;
#pragma unroll
        for (int j = 0; j < 4; j++) {
            float kj = (float)(j + 1);
            float r  = sqrtf(ki * ki + kj * kj);
            float e  = (r < 4.5f) ? (1.0f / r) : 0.0f;
            float sj = __sinf(py * (float)(j + 1));
            acc = fmaf(F[j] * e, sj, acc);
        }
        gsh[row][(isV << 2) | i] = acc;
    }
    __syncthreads();

    const int warp = tid >> 5;
    const int lane = tid & 31;
    const int row  = warp >> 2;          // which row of the pair
    const int seg  = warp & 3;           // 128-px segment within row
    const int y    = y0 + row;
    const int xb   = seg * 128 + lane;   // base pixel; +32 per k

    const float gu0 = gsh[row][0], gu1 = gsh[row][1], gu2 = gsh[row][2], gu3 = gsh[row][3];
    const float gv0 = gsh[row][4], gv1 = gsh[row][5], gv2 = gsh[row][6], gv3 = gsh[row][7];

    const int img_stride = N_ * N_;
    const char*  imgB = (const char*)(x + (size_t)b * C_ * img_stride);
    float*       orow = out + (size_t)b * C_ * img_stride + y * N_;

    // Incremental sin over k: angle step = 32 * PI_INV
    float s1 = __sinf((float)xb * PI_INV);
    float c1 = __cosf((float)xb * PI_INV);
    const float stepA = 32.0f * PI_INV;
    const float sd = __sinf(stepA);
    const float cd = __cosf(stepA);

    const float fy  = (float)y;
    // 511 - 1ulp: guarantees floor() <= 510, so the +1 taps are always
    // in-bounds and unconditional. Weight perturbation at the boundary is
    // <= 3e-5 of one inter-pixel difference (orders below tolerance).
    const float HI  = __uint_as_float(0x43FF7FFFu);   // 510.99997

#pragma unroll
    for (int k = 0; k < 4; k++) {
        const int xi = xb + k * 32;

        // harmonics from (s1, c1) via double-angle
        const float s2 = 2.0f * s1 * c1;
        const float c2 = fmaf(2.0f * c1, c1, -1.0f);
        const float s3 = fmaf(s1, c2, c1 * s2);
        const float s4 = 2.0f * s2 * c2;

        const float u = fmaf(gu0, s1, fmaf(gu1, s2, fmaf(gu2, s3, gu3 * s4)));
        const float v = fmaf(gv0, s1, fmaf(gv1, s2, fmaf(gv2, s3, gv3 * s4)));

        const float xn = fminf(fmaxf((float)xi - scale * u, 0.0f), HI);
        const float yn = fminf(fmaxf(fy        - scale * v, 0.0f), HI);

        const float xff = floorf(xn);
        const float yff = floorf(yn);
        const int   xf  = (int)xff;
        const int   yf  = (int)yff;
        const float xv  = xn - xff;
        const float yv  = yn - yff;

        const float w00 = (1.0f - yv) * (1.0f - xv);
        const float w01 = (1.0f - yv) * xv;
        const float w10 = yv * (1.0f - xv);
        const float w11 = yv * xv;

        // single base address; all 12 taps are immediate offsets from it
        const char* p = imgB + ((unsigned)(yf * N_ + xf) << 2);

#pragma unroll
        for (int c = 0; c < C_; c++) {
            const int cb = c * img_stride * 4;   // compile-time channel byte offset
            float t00 = __ldg((const float*)(p + cb));
            float t01 = __ldg((const float*)(p + cb + 4));
            float t10 = __ldg((const float*)(p + cb + 4 * N_));
            float t11 = __ldg((const float*)(p + cb + 4 * N_ + 4));
            float val = fmaf(w00, t00, fmaf(w01, t01, fmaf(w10, t10, w11 * t11)));
            orow[c * img_stride + xi] = val;     // dense 128B store per warp
        }

        // rotate (s1, c1) by 32*d
        const float ns = fmaf(s1, cd,  c1 * sd);
        const float nc = fmaf(c1, cd, -s1 * sd);
        s1 = ns; c1 = nc;
    }
}

extern "C" void kernel_launch(void* const* d_in, const int* in_sizes, int n_in,
                              void* d_out, int out_size) {
    const float* x  = (const float*)d_in[0];
    const float* Fx = (const float*)d_in[1];
    const float* Fy = (const float*)d_in[2];
    float* out = (float*)d_out;

    const double n_d  = (double)N_;
    const double typ  = n_d * sqrt(M_PI * log(4.0)) / 2.0;
    const double T    = 0.01;
    const float scale = (float)(sqrt(T / (typ * typ)) * n_d);

    dim3 block(256);
    dim3 grid(N_ / 2, B_);   // two rows per block
    diffeo_kernel<<<grid, block>>>(x, Fx, Fy, out, scale);
}